// round 10
// baseline (speedup 1.0000x reference)
#include <cuda_runtime.h>
#include <cuda_bf16.h>

// PairwiseMax: B=4096, D1=256, D2=256, F=128
// out[b, 0:256]   = x0[b,i] >= 0 ? x0[b,i]*max(x1[b,:]) : x0[b,i]*min(x1[b,:])
// out[b, 256:384] = x2[b,:]
//
// R10: R9 (best: 1024x128, warp-per-row, queue-ordered load consumption,
// REDUX reduction, branchless select) + cache-policy micro-levers:
//  - __ldg on all input loads (non-coherent read path)
//  - st.global.cs on all output stores (write-only data, evict-first:
//    keeps L2 input residency across graph replays)

#define B_ROWS 4096
#define WARPS_PER_BLOCK 4
#define THREADS (WARPS_PER_BLOCK * 32)           // 128
#define BLOCKS (B_ROWS / WARPS_PER_BLOCK)        // 1024

// Monotone map: float total order -> unsigned total order.
__device__ __forceinline__ unsigned enc_ord(float f) {
    unsigned u = __float_as_uint(f);
    return u ^ ((unsigned)((int)u >> 31) | 0x80000000u);
}
__device__ __forceinline__ float dec_ord(unsigned k) {
    return __uint_as_float(k ^ ((unsigned)(((int)~k) >> 31) | 0x80000000u));
}

// Streaming (evict-first) 128-bit store.
__device__ __forceinline__ void stg_cs(float4* p, float4 v) {
    asm volatile("st.global.cs.v4.f32 [%0], {%1, %2, %3, %4};"
                 :: "l"(p), "f"(v.x), "f"(v.y), "f"(v.z), "f"(v.w)
                 : "memory");
}

__global__ __launch_bounds__(THREADS) void pairwise_max_kernel(
    const float4* __restrict__ x0v,   // [B, 64] float4
    const float4* __restrict__ x1v,   // [B, 64] float4
    const float4* __restrict__ x2v,   // [B, 32] float4
    float4* __restrict__ outv)        // [B, 96] float4
{
    const int warp_id = threadIdx.x >> 5;
    const int lane    = threadIdx.x & 31;
    const int row     = blockIdx.x * WARPS_PER_BLOCK + warp_id;  // exact 4096

    const float4* x1row  = x1v + (size_t)row * 64;
    const float4* x0row  = x0v + (size_t)row * 64;
    const float4* x2row  = x2v + (size_t)row * 32;
    float4*       outrow = outv + (size_t)row * 96;

    // Issue x1 loads FIRST (their consumers come first), then x0/x2.
    float4 a = __ldg(x1row + lane);
    float4 b = __ldg(x1row + lane + 32);
    float4 c = __ldg(x0row + lane);
    float4 d = __ldg(x0row + lane + 32);
    float4 e = __ldg(x2row + lane);

    // First scoreboard wait: only a,b (front of the L1tex queue).
    float lmx = fmaxf(fmaxf(fmaxf(a.x, a.y), fmaxf(a.z, a.w)),
                      fmaxf(fmaxf(b.x, b.y), fmaxf(b.z, b.w)));
    float lmn = fminf(fminf(fminf(a.x, a.y), fminf(a.z, a.w)),
                      fminf(fminf(b.x, b.y), fminf(b.z, b.w)));

    // c, d, e continue landing while REDUX executes.
    const float mx = dec_ord(__reduce_max_sync(0xFFFFFFFFu, enc_ord(lmx)));
    const float mn = dec_ord(__reduce_min_sync(0xFFFFFFFFu, enc_ord(lmn)));

    // Branchless: mx >= mn, so the selected product is the larger one.
    float4 oc, od;
    oc.x = fmaxf(c.x * mx, c.x * mn);
    oc.y = fmaxf(c.y * mx, c.y * mn);
    oc.z = fmaxf(c.z * mx, c.z * mn);
    oc.w = fmaxf(c.w * mx, c.w * mn);
    od.x = fmaxf(d.x * mx, d.x * mn);
    od.y = fmaxf(d.y * mx, d.y * mn);
    od.z = fmaxf(d.z * mx, d.z * mn);
    od.w = fmaxf(d.w * mx, d.w * mn);

    stg_cs(outrow + lane,      oc);
    stg_cs(outrow + lane + 32, od);
    stg_cs(outrow + lane + 64, e);   // x2 passthrough
}

extern "C" void kernel_launch(void* const* d_in, const int* in_sizes, int n_in,
                              void* d_out, int out_size)
{
    const float4* x0v = (const float4*)d_in[0];
    const float4* x1v = (const float4*)d_in[1];
    const float4* x2v = (const float4*)d_in[2];
    float4* outv = (float4*)d_out;

    pairwise_max_kernel<<<BLOCKS, THREADS>>>(x0v, x1v, x2v, outv);
}